// round 7
// baseline (speedup 1.0000x reference)
#include <cuda_runtime.h>
#include <cuda_fp16.h>
#include <cstdint>

// ---------------------------------------------------------------------------
// IWHT3Layer, round 7: barrier-free fp16 mma.sync GEMM, A direct-from-gmem.
//   k-permutation trick: mma's k index kappa is mapped to input channel
//   c = 4*((kappa>>1)&3) + (kappa&1) + 2*((kappa>>3)&1) so each thread's
//   A-fragment quad is 4 contiguous c -> single LDG.128 + 2 cvt.f16x2.
//   B prepacked per-lane in gmem with the same permutation (L2-hot).
//   CTA 32 pixels x 64 k, 512 threads / 16 warps, warp tile m16 x n8, all
//   16 t accumulated in regs; ZERO smem, ZERO __syncthreads in mainloop.
//   Epilogue: in-register 2D WHT butterflies + bias + float2 stores.
// ---------------------------------------------------------------------------

#define U32 unsigned int
#define U64 unsigned long long

static constexpr int PIXELS   = 12544;
static constexpr int PIX_CTA  = 32;
static constexpr int NBLK     = PIXELS / PIX_CTA;   // 392
static constexpr int T_STRIDE = PIXELS * 64;
static constexpr long long OPB = 16LL * 112 * 112 * 64;

// B fragments: per (branch,t,nb,lane): 4 x U64 (kc 0..3) contiguous (32B)
__device__ __align__(16) U64 g_bfrag[3 * 16 * 8 * 32 * 4];

// ---------------- helpers ----------------
__device__ __forceinline__ U32 cvtpack(float lo, float hi) {   // f16x2, mem [lo,hi]
    U32 d; asm("cvt.rn.f16x2.f32 %0, %1, %2;" : "=r"(d) : "f"(hi), "f"(lo));
    return d;
}
__device__ __forceinline__ void mma16816(float* d, U32 a0, U32 a1, U32 a2, U32 a3,
                                         U32 b0, U32 b1) {
    asm volatile("mma.sync.aligned.m16n8k16.row.col.f32.f16.f16.f32 "
                 "{%0,%1,%2,%3}, {%4,%5,%6,%7}, {%8,%9}, {%0,%1,%2,%3};"
                 : "+f"(d[0]), "+f"(d[1]), "+f"(d[2]), "+f"(d[3])
                 : "r"(a0), "r"(a1), "r"(a2), "r"(a3), "r"(b0), "r"(b1));
}
struct F2 { float x, y; };
__device__ __forceinline__ F2 f2add(F2 a, F2 b) { return {a.x + b.x, a.y + b.y}; }
__device__ __forceinline__ F2 f2sub(F2 a, F2 b) { return {a.x - b.x, a.y - b.y}; }

// ---------------- prep: fp16 B fragments with kappa permutation ------------
__global__ void wprep_kernel(const float* __restrict__ w1,
                             const float* __restrict__ w2,
                             const float* __restrict__ w3) {
    int br = blockIdx.x >> 4, t = blockIdx.x & 15;
    const float* w = (br == 0 ? w1 : (br == 1 ? w2 : w3)) + t * 4096;
    __half* frag = (__half*)g_bfrag;
    for (int idx = threadIdx.x; idx < 4096; idx += blockDim.x) {
        int c = idx >> 6, k = idx & 63;          // w[c][k], coalesced over k
        __half h = __float2half(w[idx]);
        int kc = c >> 4, cw = c & 15;
        // kappa for this c within its 16-block (inverse of c(kappa))
        int kap = 2 * (cw >> 2) + (cw & 1) + 8 * ((cw >> 1) & 1);
        int nb = k >> 3;
        int lane = (k & 7) * 4 + ((kap >> 1) & 3);
        int regj = kap >> 3, hlf = kap & 1;
        size_t u64i = ((((size_t)(br * 16 + t) * 8 + nb) * 32 + lane) * 4 + kc);
        frag[u64i * 4 + regj * 2 + hlf] = h;
    }
}

// ---------------- main kernel ----------------
__global__ __launch_bounds__(512, 1)
void iwht_mma_kernel(const float* __restrict__ tr1, const float* __restrict__ tr2,
                     const float* __restrict__ tr3,
                     const float* __restrict__ b1, const float* __restrict__ b2,
                     const float* __restrict__ b3,
                     float* __restrict__ out) {
    const int tid  = threadIdx.x;
    const int lane = tid & 31;
    const int w    = tid >> 5;     // 0..15
    const int mb   = w & 1;        // m16 block (pixels)
    const int nb   = w >> 1;       // n8 block (k outputs)

    const int branch = blockIdx.y;
    const float* tr   = (branch == 0 ? tr1 : (branch == 1 ? tr2 : tr3));
    const float* bias = (branch == 0 ? b1  : (branch == 1 ? b2  : b3));
    const int pix0 = blockIdx.x * PIX_CTA;

    // A addressing: row = mb*16 + lane/4 (and +8), c base = kc*16 + 4*(lane%4)
    const float* xr0 = tr + (size_t)(pix0 + mb * 16 + (lane >> 2)) * 64
                          + 4 * (lane & 3);

    // B fragments: 32B contiguous per (t, warp, lane)
    const U64* gb = g_bfrag + (((size_t)branch * 16 * 8 + nb) * 32 + lane) * 4;

    float acc[16][4];
    #pragma unroll
    for (int t = 0; t < 16; t++)
        #pragma unroll
        for (int i = 0; i < 4; i++) acc[t][i] = 0.0f;

    #pragma unroll 4
    for (int t = 0; t < 16; t++) {
        // B for this t: 2x LDG.128 (L2-hot)
        const uint4* bp = (const uint4*)(gb + (size_t)t * 8 * 32 * 4);
        uint4 bv0 = bp[0], bv1 = bp[1];
        U32 bb[8] = { bv0.x, bv0.y, bv0.z, bv0.w, bv1.x, bv1.y, bv1.z, bv1.w };

        // A for this t: 8x LDG.128
        const float* xt = xr0 + (size_t)t * T_STRIDE;
        float4 v0[4], v1[4];
        #pragma unroll
        for (int kc = 0; kc < 4; kc++) {
            v0[kc] = *(const float4*)(xt + kc * 16);
            v1[kc] = *(const float4*)(xt + kc * 16 + 512);   // row + 8
        }

        #pragma unroll
        for (int kc = 0; kc < 4; kc++) {
            U32 a0 = cvtpack(v0[kc].x, v0[kc].y);
            U32 a2 = cvtpack(v0[kc].z, v0[kc].w);
            U32 a1 = cvtpack(v1[kc].x, v1[kc].y);
            U32 a3 = cvtpack(v1[kc].z, v1[kc].w);
            mma16816(acc[t], a0, a1, a2, a3, bb[kc * 2], bb[kc * 2 + 1]);
        }
    }

    // ---------------- epilogue: in-register 2D WHT + bias + stores ----------
    const int cl = lane & 3, rl = lane >> 2;
    float* outB = out + (size_t)branch * OPB;
    const int kst = nb * 8 + cl * 2;
    const float2 bv = *(const float2*)(bias + kst);

    #pragma unroll
    for (int rh = 0; rh < 2; rh++) {
        const int P = pix0 + mb * 16 + rh * 8 + rl;
        const int pb_ = P / 784, rr = P - pb_ * 784;
        const int ii = rr / 28, jj = rr - ii * 28;
        float* obase = outB + ((size_t)(pb_ * 112 + ii * 4) * 112 + jj * 4) * 64 + kst;

        // u-stage butterflies over t = 4u+v
        F2 U[4][4];
        #pragma unroll
        for (int v = 0; v < 4; v++) {
            F2 y0 = {acc[v][rh * 2],      acc[v][rh * 2 + 1]};
            F2 y1 = {acc[4 + v][rh * 2],  acc[4 + v][rh * 2 + 1]};
            F2 y2 = {acc[8 + v][rh * 2],  acc[8 + v][rh * 2 + 1]};
            F2 y3 = {acc[12 + v][rh * 2], acc[12 + v][rh * 2 + 1]};
            F2 s0 = f2add(y0, y2), s1 = f2add(y1, y3);
            F2 d0 = f2sub(y0, y2), d1 = f2sub(y1, y3);
            U[0][v] = f2add(s0, s1); U[1][v] = f2sub(s0, s1);
            U[2][v] = f2add(d0, d1); U[3][v] = f2sub(d0, d1);
        }
        #pragma unroll
        for (int p = 0; p < 4; p++) {
            F2 s0 = f2add(U[p][0], U[p][2]), s1 = f2add(U[p][1], U[p][3]);
            F2 d0 = f2sub(U[p][0], U[p][2]), d1 = f2sub(U[p][1], U[p][3]);
            F2 Z[4];
            Z[0] = f2add(s0, s1); Z[1] = f2sub(s0, s1);
            Z[2] = f2add(d0, d1); Z[3] = f2sub(d0, d1);
            float* orow = obase + (size_t)p * 7168;      // 112*64
            #pragma unroll
            for (int q = 0; q < 4; q++) {
                float zx = fmaf(Z[q].x, 0.0625f, bv.x);
                float zy = fmaf(Z[q].y, 0.0625f, bv.y);
                *(float2*)(orow + q * 64) = make_float2(zx, zy);
            }
        }
    }
}

// ---------------- launch ----------------
extern "C" void kernel_launch(void* const* d_in, const int* in_sizes, int n_in,
                              void* d_out, int out_size) {
    (void)in_sizes; (void)n_in; (void)out_size;
    const float* tr1 = (const float*)d_in[0];
    const float* tr2 = (const float*)d_in[1];
    const float* tr3 = (const float*)d_in[2];
    const float* w1  = (const float*)d_in[3];
    const float* w2  = (const float*)d_in[4];
    const float* w3  = (const float*)d_in[5];
    const float* b1  = (const float*)d_in[6];
    const float* b2  = (const float*)d_in[7];
    const float* b3  = (const float*)d_in[8];
    float* out = (float*)d_out;

    wprep_kernel<<<48, 256>>>(w1, w2, w3);
    dim3 grid(NBLK, 3);
    iwht_mma_kernel<<<grid, 512>>>(tr1, tr2, tr3, b1, b2, b3, out);
}

// round 8
// speedup vs baseline: 1.9117x; 1.9117x over previous
#include <cuda_runtime.h>
#include <cuda_fp16.h>
#include <cstdint>

// ---------------------------------------------------------------------------
// IWHT3Layer, round 8: round-5 dataflow (smem + ldmatrix + fp16 mma.sync),
// restructured for 2 CTAs/SM so barrier straggle is hidden by the co-CTA.
//   CTA: 256 threads / 8 warps / 16 pixels x 64 k x 1 branch.
//   Warp w: m16 x n8 (k = 8w..8w+7), ALL 16 t in regs (acc[16][4] = 64 regs).
//   A: x f32 LDG.128 (reg-prefetch t+1) -> f16 -> smem pitch-144B (double buf)
//      -> ldmatrix.  B: prepacked per-lane fragments, 2x LDG.128 per t, L2-hot.
//   Epilogue: in-register 2D WHT butterflies + bias + float2 stores (no shfl).
// ---------------------------------------------------------------------------

#define U32 unsigned int
#define U64 unsigned long long

static constexpr int PIXELS   = 12544;
static constexpr int PIX_CTA  = 16;
static constexpr int NBLK     = PIXELS / PIX_CTA;   // 784
static constexpr int T_STRIDE = PIXELS * 64;
static constexpr long long OPB = 16LL * 112 * 112 * 64;

static constexpr int A_PITCH  = 144;                 // conflict-free ldmatrix+STS
static constexpr int A_BUF    = 16 * A_PITCH;        // 2304 B per buffer

// B fragments: per (branch,t,nb,lane): 4 x U64 (kc 0..3) contiguous (32B)
__device__ __align__(16) U64 g_bfrag[3 * 16 * 8 * 32 * 4];

// ---------------- helpers ----------------
__device__ __forceinline__ U32 smem_u32(const void* p) {
    U32 a; asm("{ .reg .u64 t; cvta.to.shared.u64 t, %1; cvt.u32.u64 %0, t; }"
               : "=r"(a) : "l"(p)); return a;
}
__device__ __forceinline__ void ldm4(U32& a0, U32& a1, U32& a2, U32& a3, U32 addr) {
    asm volatile("ldmatrix.sync.aligned.m8n8.x4.shared.b16 {%0,%1,%2,%3}, [%4];"
                 : "=r"(a0), "=r"(a1), "=r"(a2), "=r"(a3) : "r"(addr));
}
__device__ __forceinline__ void mma16816(float* d, U32 a0, U32 a1, U32 a2, U32 a3,
                                         U32 b0, U32 b1) {
    asm volatile("mma.sync.aligned.m16n8k16.row.col.f32.f16.f16.f32 "
                 "{%0,%1,%2,%3}, {%4,%5,%6,%7}, {%8,%9}, {%0,%1,%2,%3};"
                 : "+f"(d[0]), "+f"(d[1]), "+f"(d[2]), "+f"(d[3])
                 : "r"(a0), "r"(a1), "r"(a2), "r"(a3), "r"(b0), "r"(b1));
}
struct F2 { float x, y; };
__device__ __forceinline__ F2 f2add(F2 a, F2 b) { return {a.x + b.x, a.y + b.y}; }
__device__ __forceinline__ F2 f2sub(F2 a, F2 b) { return {a.x - b.x, a.y - b.y}; }

// ---------------- prep: build fp16 B fragments (one-time) ----------------
__global__ void wprep_kernel(const float* __restrict__ w1,
                             const float* __restrict__ w2,
                             const float* __restrict__ w3) {
    int br = blockIdx.x >> 4, t = blockIdx.x & 15;
    const float* w = (br == 0 ? w1 : (br == 1 ? w2 : w3)) + t * 4096;
    __half* frag = (__half*)g_bfrag;
    for (int idx = threadIdx.x; idx < 4096; idx += blockDim.x) {
        int c = idx >> 6, k = idx & 63;          // w[c][k], coalesced over k
        __half h = __float2half(w[idx]);
        int kc = c >> 4, cw = c & 15;
        int nb = k >> 3, lane = (k & 7) * 4 + ((cw & 7) >> 1);
        int regj = cw >> 3, hlf = cw & 1;
        size_t u64i = ((((size_t)(br * 16 + t) * 8 + nb) * 32 + lane) * 4 + kc);
        frag[u64i * 4 + regj * 2 + hlf] = h;
    }
}

// ---------------- main kernel ----------------
__global__ __launch_bounds__(256, 2)
void iwht_mma_kernel(const float* __restrict__ tr1, const float* __restrict__ tr2,
                     const float* __restrict__ tr3,
                     const float* __restrict__ b1, const float* __restrict__ b2,
                     const float* __restrict__ b3,
                     float* __restrict__ out) {
    __shared__ __align__(16) char asm_buf[2 * A_BUF];   // 4608 B

    const int tid  = threadIdx.x;
    const int lane = tid & 31;
    const int w    = tid >> 5;     // 0..7 -> n8 block (k outputs)

    const int branch = blockIdx.y;
    const float* tr   = (branch == 0 ? tr1 : (branch == 1 ? tr2 : tr3));
    const float* bias = (branch == 0 ? b1  : (branch == 1 ? b2  : b3));
    const int pix0 = blockIdx.x * PIX_CTA;

    // staging role: thread -> (row 0..15, 4 floats at cseg*4)
    const int crow = tid >> 4, cseg = tid & 15;
    const float* xrow = tr + (size_t)(pix0 + crow) * 64 + cseg * 4;

    auto cvtStore = [&](float4 a, int buf) {
        __half2 h0 = __floats2half2_rn(a.x, a.y);
        __half2 h1 = __floats2half2_rn(a.z, a.w);
        *(uint2*)(asm_buf + buf * A_BUF + crow * A_PITCH + cseg * 8) =
            make_uint2(*reinterpret_cast<U32*>(&h0), *reinterpret_cast<U32*>(&h1));
    };

    // B fragments: 32B contiguous per (t, warp, lane)
    const U64* gb = g_bfrag + (((size_t)branch * 16 * 8 + w) * 32 + lane) * 4;
    auto loadB = [&](int t, U64* dst) {
        const uint4* p = (const uint4*)(gb + (size_t)t * 8 * 32 * 4);
        uint4 v0 = p[0], v1 = p[1];
        dst[0] = (U64)v0.x | ((U64)v0.y << 32);
        dst[1] = (U64)v0.z | ((U64)v0.w << 32);
        dst[2] = (U64)v1.x | ((U64)v1.y << 32);
        dst[3] = (U64)v1.z | ((U64)v1.w << 32);
    };

    // prologue
    cvtStore(*(const float4*)xrow, 0);
    U64 bcur[4], bnxt[4];
    loadB(0, bcur);
    __syncthreads();

    const U32 sbase = smem_u32(asm_buf);
    const U32 arow0 = sbase + (U32)((lane & 15) * A_PITCH + (lane >> 4) * 16);

    float acc[16][4];
    #pragma unroll
    for (int t = 0; t < 16; t++)
        #pragma unroll
        for (int i = 0; i < 4; i++) acc[t][i] = 0.0f;

    #pragma unroll
    for (int t = 0; t < 16; t++) {
        // prefetch x(t+1) and B(t+1)
        float4 pa;
        if (t < 15) {
            pa = *(const float4*)(xrow + (size_t)(t + 1) * T_STRIDE);
            loadB(t + 1, bnxt);
        }

        // MMAs for t
        const U32 ab = arow0 + (U32)((t & 1) * A_BUF);
        #pragma unroll
        for (int kc = 0; kc < 4; kc++) {
            U32 a0, a1, a2, a3;
            ldm4(a0, a1, a2, a3, ab + kc * 32);
            mma16816(acc[t], a0, a1, a2, a3,
                     (U32)bcur[kc], (U32)(bcur[kc] >> 32));
        }

        if (t < 15) {
            cvtStore(pa, (t + 1) & 1);
            #pragma unroll
            for (int kc = 0; kc < 4; kc++) bcur[kc] = bnxt[kc];
        }
        __syncthreads();
    }

    // ---------------- epilogue: in-register 2D WHT + bias + stores ----------
    const int cl = lane & 3, rl = lane >> 2;
    float* outB = out + (size_t)branch * OPB;
    const int kst = w * 8 + cl * 2;
    const float2 bv = *(const float2*)(bias + kst);

    #pragma unroll
    for (int rh = 0; rh < 2; rh++) {
        const int P = pix0 + rh * 8 + rl;
        const int pb_ = P / 784, rr = P - pb_ * 784;
        const int ii = rr / 28, jj = rr - ii * 28;
        float* obase = outB + ((size_t)(pb_ * 112 + ii * 4) * 112 + jj * 4) * 64 + kst;

        // u-stage butterflies over t = 4u+v
        F2 U[4][4];
        #pragma unroll
        for (int v = 0; v < 4; v++) {
            F2 y0 = {acc[v][rh * 2],      acc[v][rh * 2 + 1]};
            F2 y1 = {acc[4 + v][rh * 2],  acc[4 + v][rh * 2 + 1]};
            F2 y2 = {acc[8 + v][rh * 2],  acc[8 + v][rh * 2 + 1]};
            F2 y3 = {acc[12 + v][rh * 2], acc[12 + v][rh * 2 + 1]};
            F2 s0 = f2add(y0, y2), s1 = f2add(y1, y3);
            F2 d0 = f2sub(y0, y2), d1 = f2sub(y1, y3);
            U[0][v] = f2add(s0, s1); U[1][v] = f2sub(s0, s1);
            U[2][v] = f2add(d0, d1); U[3][v] = f2sub(d0, d1);
        }
        #pragma unroll
        for (int p = 0; p < 4; p++) {
            F2 s0 = f2add(U[p][0], U[p][2]), s1 = f2add(U[p][1], U[p][3]);
            F2 d0 = f2sub(U[p][0], U[p][2]), d1 = f2sub(U[p][1], U[p][3]);
            F2 Z[4];
            Z[0] = f2add(s0, s1); Z[1] = f2sub(s0, s1);
            Z[2] = f2add(d0, d1); Z[3] = f2sub(d0, d1);
            float* orow = obase + (size_t)p * 7168;      // 112*64
            #pragma unroll
            for (int q = 0; q < 4; q++) {
                float zx = fmaf(Z[q].x, 0.0625f, bv.x);
                float zy = fmaf(Z[q].y, 0.0625f, bv.y);
                *(float2*)(orow + q * 64) = make_float2(zx, zy);
            }
        }
    }
}

// ---------------- launch ----------------
extern "C" void kernel_launch(void* const* d_in, const int* in_sizes, int n_in,
                              void* d_out, int out_size) {
    (void)in_sizes; (void)n_in; (void)out_size;
    const float* tr1 = (const float*)d_in[0];
    const float* tr2 = (const float*)d_in[1];
    const float* tr3 = (const float*)d_in[2];
    const float* w1  = (const float*)d_in[3];
    const float* w2  = (const float*)d_in[4];
    const float* w3  = (const float*)d_in[5];
    const float* b1  = (const float*)d_in[6];
    const float* b2  = (const float*)d_in[7];
    const float* b3  = (const float*)d_in[8];
    float* out = (float*)d_out;

    wprep_kernel<<<48, 256>>>(w1, w2, w3);
    dim3 grid(NBLK, 3);
    iwht_mma_kernel<<<grid, 256>>>(tr1, tr2, tr3, b1, b2, b3, out);
}